// round 6
// baseline (speedup 1.0000x reference)
#include <cuda_runtime.h>
#include <cuda_bf16.h>
#include <math.h>

#define H    2048
#define E    64
#define TOPK 4
#define SW   1024
#define Bsz  2
#define S    4096
#define NEGF (-3.402823466e+38f)
#define EPS  1e-6f
#define INV_SQRT_H 0.02209708691207961f   // 1/sqrt(2048)

#define NTOK   (Bsz * S)          // 8192 tokens
#define KSPLIT 4
#define KSEG   (H / KSPLIT)       // 512
#define KC     32                 // k chunk per stage
#define NSTAGE (KSEG / KC)        // 16
#define TMB    256                // tokens per gemm block
#define XSTR   36                 // padded smem row stride (floats)

#define XS_FLOATS (TMB * XSTR)    // 9216
#define WS_FLOATS (E * XSTR)      // 2304
#define BUF_FLOATS (XS_FLOATS + WS_FLOATS)
#define SMEM_GEMM (2 * BUF_FLOATS * 4)   // 92160 bytes

typedef unsigned long long ull;

// scratch (__device__ globals: allocation-free)
__device__ int   g_gid[Bsz * S];
__device__ int   g_vstart[Bsz * S];
__device__ int   g_vend[Bsz * S];
__device__ int   g_dstart[Bsz * 8];
__device__ int   g_dend[Bsz * 8];
__device__ float g_wp[E * H];                  // proj_w * scale * H^-0.5
__device__ float g_plog[KSPLIT * NTOK * E];    // partial logits (8 MB)
__device__ float g_ss[KSPLIT * NTOK];          // partial sum-of-squares

__device__ __forceinline__ void fma_f32x2(ull& d, ull a, ull b) {
    asm("fma.rn.f32x2 %0, %1, %2, %0;" : "+l"(d) : "l"(a), "l"(b));
}

__device__ __forceinline__ void cp16(void* dst_smem, const void* src) {
    unsigned d = (unsigned)__cvta_generic_to_shared(dst_smem);
    asm volatile("cp.async.cg.shared.global [%0], [%1], 16;" :: "r"(d), "l"(src));
}

// ---------------------------------------------------------------------------
// Kernel 1: vision group ids + doc/vision interval endpoints
// ---------------------------------------------------------------------------
__global__ void __launch_bounds__(1024) gid_kernel(const int* __restrict__ mm,
                                                   const int* __restrict__ packed) {
    const int b = blockIdx.x;
    const int* m = mm + b * S;
    const int* p = packed + b * S;
    int* g = g_gid + b * S;
    const int t = threadIdx.x;
    const int lane = t & 31, warp = t >> 5;
    const int base = t * 4;

    int isv[5], st[4];
    int cnt = 0;
#pragma unroll
    for (int i = 0; i < 4; i++) {
        int pos = base + i;
        int mv = m[pos];
        int v = (mv == 1 || mv == 2) ? 1 : 0;
        int pv = 0;
        if (pos > 0) {
            int pm = m[pos - 1];
            pv = (pm == 1 || pm == 2) ? 1 : 0;
        }
        int s = (v && !pv) ? 1 : 0;
        isv[i] = v; st[i] = s; cnt += s;
    }
    {
        int pos = base + 4;
        int nv = 0;
        if (pos < S) {
            int nm = m[pos];
            nv = (nm == 1 || nm == 2) ? 1 : 0;
        }
        isv[4] = nv;
    }

    // doc interval endpoints (packed is sorted per row, ids 0..4)
#pragma unroll
    for (int i = 0; i < 4; i++) {
        int pos = base + i;
        int v = p[pos];
        int prev = (pos > 0) ? p[pos - 1] : -1;
        int next = (pos < S - 1) ? p[pos + 1] : -1;
        if (v != prev && v >= 0 && v < 8) g_dstart[b * 8 + v] = pos;
        if (v != next && v >= 0 && v < 8) g_dend[b * 8 + v] = pos;
    }

    // warp inclusive scan
    int inc = cnt;
#pragma unroll
    for (int off = 1; off < 32; off <<= 1) {
        int v = __shfl_up_sync(0xffffffffu, inc, off);
        if (lane >= off) inc += v;
    }
    __shared__ int wsum[32];
    if (lane == 31) wsum[warp] = inc;
    __syncthreads();
    if (warp == 0) {
        int v = wsum[lane];
#pragma unroll
        for (int off = 1; off < 32; off <<= 1) {
            int u = __shfl_up_sync(0xffffffffu, v, off);
            if (lane >= off) v += u;
        }
        wsum[lane] = v;
    }
    __syncthreads();
    int run = ((warp > 0) ? wsum[warp - 1] : 0) + inc - cnt;
#pragma unroll
    for (int i = 0; i < 4; i++) {
        run += st[i];
        int pos = base + i;
        int gv = isv[i] ? (run - 1) : -1;
        g[pos] = gv;
        if (gv >= 0) {
            if (st[i]) g_vstart[b * S + gv] = pos;
            if (!isv[i + 1] || pos == S - 1) g_vend[b * S + gv] = pos;
        }
    }
}

// ---------------------------------------------------------------------------
// Kernel 2: masks as interval fills. grid = (S, B), 256 threads.
// ---------------------------------------------------------------------------
__global__ void __launch_bounds__(256) mask_kernel(const int* __restrict__ packed,
                                                   float* __restrict__ full_out,
                                                   float* __restrict__ slid_out) {
    const int q = blockIdx.x;
    const int b = blockIdx.y;
    const int pq = __ldg(&packed[b * S + q]);

    int flo = 1, fhi = 0;
    int alo = 1, ahi = 0;
    int clo = 1, chi = 0;
    if (pq > 0) {
        const int dlo = g_dstart[b * 8 + pq];
        const int dhi = g_dend[b * 8 + pq];
        flo = dlo; fhi = q;
        alo = max(dlo, q - SW + 1); ahi = q;
        const int gq = g_gid[b * S + q];
        if (gq >= 0) {
            clo = max(g_vstart[b * S + gq], dlo);
            chi = min(g_vend[b * S + gq], dhi);
        }
    }

    const size_t rowoff = ((size_t)b * S + (size_t)q) * (size_t)S;
    float4* fo = (float4*)(full_out + rowoff);
    float4* so = (float4*)(slid_out + rowoff);

#pragma unroll
    for (int it = 0; it < 4; it++) {
        const int c = threadIdx.x + it * 256;
        const int kv = c * 4;
        float4 f, sl;
        f.x = (kv + 0 >= flo && kv + 0 <= fhi) ? 0.0f : NEGF;
        f.y = (kv + 1 >= flo && kv + 1 <= fhi) ? 0.0f : NEGF;
        f.z = (kv + 2 >= flo && kv + 2 <= fhi) ? 0.0f : NEGF;
        f.w = (kv + 3 >= flo && kv + 3 <= fhi) ? 0.0f : NEGF;
        sl.x = ((kv + 0 >= alo && kv + 0 <= ahi) || (kv + 0 >= clo && kv + 0 <= chi)) ? 0.0f : NEGF;
        sl.y = ((kv + 1 >= alo && kv + 1 <= ahi) || (kv + 1 >= clo && kv + 1 <= chi)) ? 0.0f : NEGF;
        sl.z = ((kv + 2 >= alo && kv + 2 <= ahi) || (kv + 2 >= clo && kv + 2 <= chi)) ? 0.0f : NEGF;
        sl.w = ((kv + 3 >= alo && kv + 3 <= ahi) || (kv + 3 >= clo && kv + 3 <= chi)) ? 0.0f : NEGF;
        __stcs(&fo[c], f);
        __stcs(&so[c], sl);
    }
}

// ---------------------------------------------------------------------------
// Kernel 3: fold scale*H^-0.5 into proj_w
// ---------------------------------------------------------------------------
__global__ void __launch_bounds__(256) wp_kernel(const float* __restrict__ proj_w,
                                                 const float* __restrict__ scale) {
    int i = blockIdx.x * 256 + threadIdx.x;
    if (i < E * H) {
        g_wp[i] = proj_w[i] * scale[i & (H - 1)] * INV_SQRT_H;
    }
}

// ---------------------------------------------------------------------------
// Kernel 4: gate GEMM, split-K, cp.async double-buffered.
// grid = (32, 4). Block: 256 tokens x 64 experts over K=512. 256 threads,
// 8x8 thread tile, f32x2 FMA. Sum-of-squares folded into compute (tc==0).
// ---------------------------------------------------------------------------
__device__ __forceinline__ void gemm_prefetch(const float* __restrict__ x,
                                              int n0, int kb, int tid,
                                              float* xsb, float* wsb) {
#pragma unroll
    for (int j = 0; j < 8; j++) {
        int idx = tid + j * 256;
        int row = idx >> 3;
        int col = idx & 7;
        cp16(&xsb[row * XSTR + col * 4], x + (size_t)(n0 + row) * H + kb + col * 4);
    }
#pragma unroll
    for (int j = 0; j < 2; j++) {
        int idx = tid + j * 256;
        int row = idx >> 3;
        int col = idx & 7;
        cp16(&wsb[row * XSTR + col * 4], g_wp + (size_t)row * H + kb + col * 4);
    }
    asm volatile("cp.async.commit_group;");
}

__global__ void __launch_bounds__(256) gate_gemm(const float* __restrict__ x) {
    extern __shared__ float sm[];
    const int n0 = blockIdx.x * TMB;
    const int ks = blockIdx.y;
    const int kb0 = ks * KSEG;

    float* xs[2] = { sm, sm + BUF_FLOATS };
    float* ws[2] = { sm + XS_FLOATS, sm + BUF_FLOATS + XS_FLOATS };

    const int tid = threadIdx.x;
    const int tr = tid >> 3;    // 0..31 token group
    const int tc = tid & 7;     // 0..7 expert group

    ull acc[8][8];
#pragma unroll
    for (int i = 0; i < 8; i++)
#pragma unroll
        for (int j = 0; j < 8; j++) acc[i][j] = 0ull;
    float ssp[8];
#pragma unroll
    for (int i = 0; i < 8; i++) ssp[i] = 0.0f;

    gemm_prefetch(x, n0, kb0, tid, xs[0], ws[0]);

    for (int s = 0; s < NSTAGE; s++) {
        if (s + 1 < NSTAGE) {
            gemm_prefetch(x, n0, kb0 + (s + 1) * KC, tid, xs[(s + 1) & 1], ws[(s + 1) & 1]);
            asm volatile("cp.async.wait_group 1;" ::: "memory");
        } else {
            asm volatile("cp.async.wait_group 0;" ::: "memory");
        }
        __syncthreads();

        const float* xsb = xs[s & 1];
        const float* wsb = ws[s & 1];
#pragma unroll
        for (int k4 = 0; k4 < KC / 4; k4++) {
            ulonglong2 A[8];
#pragma unroll
            for (int i = 0; i < 8; i++)
                A[i] = *(const ulonglong2*)&xsb[(tr + 32 * i) * XSTR + k4 * 4];
            if (tc == 0) {
#pragma unroll
                for (int i = 0; i < 8; i++) {
                    float2 lo = *(float2*)&A[i].x;
                    float2 hi = *(float2*)&A[i].y;
                    ssp[i] += lo.x * lo.x + lo.y * lo.y + hi.x * hi.x + hi.y * hi.y;
                }
            }
#pragma unroll
            for (int j = 0; j < 8; j++) {
                ulonglong2 Bv = *(const ulonglong2*)&wsb[(tc + 8 * j) * XSTR + k4 * 4];
#pragma unroll
                for (int i = 0; i < 8; i++) {
                    fma_f32x2(acc[i][j], A[i].x, Bv.x);
                    fma_f32x2(acc[i][j], A[i].y, Bv.y);
                }
            }
        }
        __syncthreads();
    }

    // sum-of-squares: tc==0 threads own rows tr+32i exclusively
    if (tc == 0) {
#pragma unroll
        for (int i = 0; i < 8; i++)
            g_ss[ks * NTOK + n0 + tr + 32 * i] = ssp[i];
    }

    // write partial logits
#pragma unroll
    for (int i = 0; i < 8; i++) {
        const int n = n0 + tr + 32 * i;
#pragma unroll
        for (int j = 0; j < 8; j++) {
            float2 p = *(float2*)&acc[i][j];
            g_plog[(size_t)ks * NTOK * E + (size_t)n * E + tc + 8 * j] = p.x + p.y;
        }
    }
}

// ---------------------------------------------------------------------------
// Kernel 5: reduce split-K, rms factor, top-4. One warp per token.
// grid = NTOK/8 = 1024 blocks, 256 threads.
// ---------------------------------------------------------------------------
__global__ void __launch_bounds__(256) gate_final(float* __restrict__ out_w,
                                                  float* __restrict__ out_i) {
    const int warp = threadIdx.x >> 5;
    const int lane = threadIdx.x & 31;
    const int n = blockIdx.x * 8 + warp;

    float l0 = 0.0f, l1 = 0.0f, ss = 0.0f;
#pragma unroll
    for (int ks = 0; ks < KSPLIT; ks++) {
        const float* p = g_plog + (size_t)ks * NTOK * E + (size_t)n * E;
        l0 += p[lane];
        l1 += p[lane + 32];
        ss += g_ss[ks * NTOK + n];
    }
    const float f = rsqrtf(ss * (1.0f / H) + EPS);
    l0 *= f; l1 *= f;

    float wk[TOPK]; int ik[TOPK];
#pragma unroll
    for (int k = 0; k < TOPK; k++) {
        // lane-local argmax over {e=lane, e=lane+32}; lower index wins ties
        float v = l0; int idx = lane;
        if (l1 > v) { v = l1; idx = lane + 32; }
        // warp butterfly argmax: lower index wins ties (matches jax.lax.top_k)
#pragma unroll
        for (int off = 16; off; off >>= 1) {
            float ov = __shfl_xor_sync(0xffffffffu, v, off);
            int   oi = __shfl_xor_sync(0xffffffffu, idx, off);
            if (ov > v || (ov == v && oi < idx)) { v = ov; idx = oi; }
        }
        wk[k] = v; ik[k] = idx;
        if (idx == lane)      l0 = -3.4e38f;
        if (idx == lane + 32) l1 = -3.4e38f;
    }

    if (lane == 0) {
        const float m = wk[0];
        float p[TOPK], psum = 0.0f;
#pragma unroll
        for (int k = 0; k < TOPK; k++) { p[k] = __expf(wk[k] - m); psum += p[k]; }
        const float inv = 1.0f / fmaxf(psum, 1e-20f);
#pragma unroll
        for (int k = 0; k < TOPK; k++) {
            out_w[n * TOPK + k] = p[k] * inv;
            out_i[n * TOPK + k] = (float)ik[k];
        }
    }
}

// ---------------------------------------------------------------------------
extern "C" void kernel_launch(void* const* d_in, const int* in_sizes, int n_in,
                              void* d_out, int out_size) {
    const float* x      = (const float*)d_in[0];   // [B,S,H]
    const int*   packed = (const int*)  d_in[1];   // [B,S]
    const int*   mm     = (const int*)  d_in[2];   // [B,S]
    const float* scale  = (const float*)d_in[3];   // [H]
    const float* proj_w = (const float*)d_in[4];   // [E,H]

    float* out = (float*)d_out;
    const size_t mask_elems = (size_t)Bsz * S * S;           // 33554432
    float* full_out = out;
    float* slid_out = out + mask_elems;
    float* wts_out  = out + 2 * mask_elems;
    float* idx_out  = wts_out + (size_t)NTOK * TOPK;

    // one-time resources (identical GPU work every call)
    static cudaStream_t s2 = nullptr;
    static cudaEvent_t evA = nullptr, evB = nullptr;
    if (s2 == nullptr) {
        cudaStreamCreateWithFlags(&s2, cudaStreamNonBlocking);
        cudaEventCreateWithFlags(&evA, cudaEventDisableTiming);
        cudaEventCreateWithFlags(&evB, cudaEventDisableTiming);
        cudaFuncSetAttribute(gate_gemm, cudaFuncAttributeMaxDynamicSharedMemorySize, SMEM_GEMM);
    }

    gid_kernel<<<Bsz, 1024>>>(mm, packed);

    // fork: mask (depends only on gid) runs concurrently with gate chain
    cudaEventRecord(evA, 0);
    cudaStreamWaitEvent(s2, evA, 0);
    mask_kernel<<<dim3(S, Bsz), 256, 0, s2>>>(packed, full_out, slid_out);
    cudaEventRecord(evB, s2);

    wp_kernel<<<(E * H + 255) / 256, 256>>>(proj_w, scale);
    gate_gemm<<<dim3(NTOK / TMB, KSPLIT), 256, SMEM_GEMM>>>(x);
    gate_final<<<NTOK / 8, 256>>>(wts_out, idx_out);

    // join
    cudaStreamWaitEvent(0, evB, 0);
}

// round 12
// speedup vs baseline: 1.0806x; 1.0806x over previous
#include <cuda_runtime.h>
#include <cuda_bf16.h>
#include <math.h>

#define H    2048
#define E    64
#define TOPK 4
#define SW   1024
#define Bsz  2
#define S    4096
#define NEGF (-3.402823466e+38f)
#define EPS  1e-6f
#define INV_SQRT_H 0.02209708691207961f   // 1/sqrt(2048)

#define NTOK   (Bsz * S)          // 8192 tokens
#define KSPLIT 8
#define KSEG   (H / KSPLIT)       // 256
#define KC     32                 // k chunk per stage
#define NSTAGE (KSEG / KC)        // 8
#define TMB    256                // tokens per gemm block
#define XTSTR  258                // xs_t row stride (floats) - EVEN (LDS.64 aligned), conflict-free
#define WDSTR  33                 // ws_dup row stride (f32x2) - conflict-free

#define SMEM_GEMM (KC * XTSTR * 4 + E * WDSTR * 8)   // 33024 + 16896 = 49920 B

typedef unsigned long long ull;

// scratch (__device__ globals: allocation-free)
__device__ int   g_gid[Bsz * S];
__device__ int   g_vstart[Bsz * S];
__device__ int   g_vend[Bsz * S];
__device__ int   g_dstart[Bsz * 8];
__device__ int   g_dend[Bsz * 8];
__device__ float g_wp[E * H];                  // proj_w * scale * H^-0.5
__device__ float g_plog[KSPLIT * NTOK * E];    // partial logits
__device__ float g_ss[KSPLIT * NTOK];          // partial sum-of-squares

__device__ __forceinline__ void fma_f32x2(ull& d, ull a, ull b) {
    asm("fma.rn.f32x2 %0, %1, %2, %0;" : "+l"(d) : "l"(a), "l"(b));
}

// ---------------------------------------------------------------------------
// Kernel 1: vision group ids + doc/vision interval endpoints
// ---------------------------------------------------------------------------
__global__ void __launch_bounds__(1024) gid_kernel(const int* __restrict__ mm,
                                                   const int* __restrict__ packed) {
    const int b = blockIdx.x;
    const int* m = mm + b * S;
    const int* p = packed + b * S;
    int* g = g_gid + b * S;
    const int t = threadIdx.x;
    const int lane = t & 31, warp = t >> 5;
    const int base = t * 4;

    int isv[5], st[4];
    int cnt = 0;
#pragma unroll
    for (int i = 0; i < 4; i++) {
        int pos = base + i;
        int mv = m[pos];
        int v = (mv == 1 || mv == 2) ? 1 : 0;
        int pv = 0;
        if (pos > 0) {
            int pm = m[pos - 1];
            pv = (pm == 1 || pm == 2) ? 1 : 0;
        }
        int s = (v && !pv) ? 1 : 0;
        isv[i] = v; st[i] = s; cnt += s;
    }
    {
        int pos = base + 4;
        int nv = 0;
        if (pos < S) {
            int nm = m[pos];
            nv = (nm == 1 || nm == 2) ? 1 : 0;
        }
        isv[4] = nv;
    }

    // doc interval endpoints (packed is sorted per row, ids 0..4)
#pragma unroll
    for (int i = 0; i < 4; i++) {
        int pos = base + i;
        int v = p[pos];
        int prev = (pos > 0) ? p[pos - 1] : -1;
        int next = (pos < S - 1) ? p[pos + 1] : -1;
        if (v != prev && v >= 0 && v < 8) g_dstart[b * 8 + v] = pos;
        if (v != next && v >= 0 && v < 8) g_dend[b * 8 + v] = pos;
    }

    // warp inclusive scan
    int inc = cnt;
#pragma unroll
    for (int off = 1; off < 32; off <<= 1) {
        int v = __shfl_up_sync(0xffffffffu, inc, off);
        if (lane >= off) inc += v;
    }
    __shared__ int wsum[32];
    if (lane == 31) wsum[warp] = inc;
    __syncthreads();
    if (warp == 0) {
        int v = wsum[lane];
#pragma unroll
        for (int off = 1; off < 32; off <<= 1) {
            int u = __shfl_up_sync(0xffffffffu, v, off);
            if (lane >= off) v += u;
        }
        wsum[lane] = v;
    }
    __syncthreads();
    int run = ((warp > 0) ? wsum[warp - 1] : 0) + inc - cnt;
#pragma unroll
    for (int i = 0; i < 4; i++) {
        run += st[i];
        int pos = base + i;
        int gv = isv[i] ? (run - 1) : -1;
        g[pos] = gv;
        if (gv >= 0) {
            if (st[i]) g_vstart[b * S + gv] = pos;
            if (!isv[i + 1] || pos == S - 1) g_vend[b * S + gv] = pos;
        }
    }
}

// ---------------------------------------------------------------------------
// Kernel 2: masks as interval fills. grid = (S, B), 256 threads.
// ---------------------------------------------------------------------------
__global__ void __launch_bounds__(256) mask_kernel(const int* __restrict__ packed,
                                                   float* __restrict__ full_out,
                                                   float* __restrict__ slid_out) {
    const int q = blockIdx.x;
    const int b = blockIdx.y;
    const int pq = __ldg(&packed[b * S + q]);

    int flo = 1, fhi = 0;
    int alo = 1, ahi = 0;
    int clo = 1, chi = 0;
    if (pq > 0) {
        const int dlo = g_dstart[b * 8 + pq];
        const int dhi = g_dend[b * 8 + pq];
        flo = dlo; fhi = q;
        alo = max(dlo, q - SW + 1); ahi = q;
        const int gq = g_gid[b * S + q];
        if (gq >= 0) {
            clo = max(g_vstart[b * S + gq], dlo);
            chi = min(g_vend[b * S + gq], dhi);
        }
    }

    const size_t rowoff = ((size_t)b * S + (size_t)q) * (size_t)S;
    float4* fo = (float4*)(full_out + rowoff);
    float4* so = (float4*)(slid_out + rowoff);

#pragma unroll
    for (int it = 0; it < 4; it++) {
        const int c = threadIdx.x + it * 256;
        const int kv = c * 4;
        float4 f, sl;
        f.x = (kv + 0 >= flo && kv + 0 <= fhi) ? 0.0f : NEGF;
        f.y = (kv + 1 >= flo && kv + 1 <= fhi) ? 0.0f : NEGF;
        f.z = (kv + 2 >= flo && kv + 2 <= fhi) ? 0.0f : NEGF;
        f.w = (kv + 3 >= flo && kv + 3 <= fhi) ? 0.0f : NEGF;
        sl.x = ((kv + 0 >= alo && kv + 0 <= ahi) || (kv + 0 >= clo && kv + 0 <= chi)) ? 0.0f : NEGF;
        sl.y = ((kv + 1 >= alo && kv + 1 <= ahi) || (kv + 1 >= clo && kv + 1 <= chi)) ? 0.0f : NEGF;
        sl.z = ((kv + 2 >= alo && kv + 2 <= ahi) || (kv + 2 >= clo && kv + 2 <= chi)) ? 0.0f : NEGF;
        sl.w = ((kv + 3 >= alo && kv + 3 <= ahi) || (kv + 3 >= clo && kv + 3 <= chi)) ? 0.0f : NEGF;
        __stcs(&fo[c], f);
        __stcs(&so[c], sl);
    }
}

// ---------------------------------------------------------------------------
// Kernel 3: fold scale*H^-0.5 into proj_w
// ---------------------------------------------------------------------------
__global__ void __launch_bounds__(256) wp_kernel(const float* __restrict__ proj_w,
                                                 const float* __restrict__ scale) {
    int i = blockIdx.x * 256 + threadIdx.x;
    if (i < E * H) {
        g_wp[i] = proj_w[i] * scale[i & (H - 1)] * INV_SQRT_H;
    }
}

// ---------------------------------------------------------------------------
// Kernel 4: gate GEMM, split-K. grid = (NTOK/TMB, KSPLIT) = (32, 8).
// 256 threads, 2 blocks/SM. Token-pair-packed f32x2 accumulators:
//   acc[4 token-pairs][8 experts] = 64 regs.
// x stored k-major (xs_t[k][token], stride 258), w duplicated
// (ws_dup[e][k]=(w,w), stride 33 pairs). Inner loop per k:
//   4 LDS.64 (a pairs) + 8 LDS.64 (b dups) + 32 FFMA2.
// ---------------------------------------------------------------------------
__global__ void __launch_bounds__(256, 2) gate_gemm(const float* __restrict__ x) {
    extern __shared__ float sm[];
    float* xs_t = sm;                                   // [KC][XTSTR]
    float2* wsd = (float2*)(sm + KC * XTSTR);           // [E][WDSTR]

    const int n0 = blockIdx.x * TMB;
    const int ks = blockIdx.y;
    const int kb0 = ks * KSEG;

    const int tid = threadIdx.x;
    const int tr = tid >> 3;    // 0..31 token-pair group
    const int tc = tid & 7;     // 0..7 expert group

    ull acc[4][8];
#pragma unroll
    for (int i = 0; i < 4; i++)
#pragma unroll
        for (int j = 0; j < 8; j++) acc[i][j] = 0ull;
    float ssp[8];
#pragma unroll
    for (int j = 0; j < 8; j++) ssp[j] = 0.0f;

    for (int s = 0; s < NSTAGE; s++) {
        const int kb = kb0 + s * KC;
        // load x tile [256 tokens][32 k] -> transpose into xs_t[k][token]
#pragma unroll
        for (int j = 0; j < 8; j++) {
            int idx = tid + j * 256;
            int row = idx >> 3;       // token 0..255
            int col = idx & 7;        // k-group 0..7
            float4 v = *(const float4*)(x + (size_t)(n0 + row) * H + kb + col * 4);
            ssp[j] += v.x * v.x + v.y * v.y + v.z * v.z + v.w * v.w;
            xs_t[(col * 4 + 0) * XTSTR + row] = v.x;
            xs_t[(col * 4 + 1) * XTSTR + row] = v.y;
            xs_t[(col * 4 + 2) * XTSTR + row] = v.z;
            xs_t[(col * 4 + 3) * XTSTR + row] = v.w;
        }
        // load w tile [64 experts][32 k] -> duplicated pairs
#pragma unroll
        for (int j = 0; j < 2; j++) {
            int idx = tid + j * 256;
            int e = idx >> 3;
            int k4 = idx & 7;
            float4 v = *(const float4*)(g_wp + (size_t)e * H + kb + k4 * 4);
            wsd[e * WDSTR + k4 * 4 + 0] = make_float2(v.x, v.x);
            wsd[e * WDSTR + k4 * 4 + 1] = make_float2(v.y, v.y);
            wsd[e * WDSTR + k4 * 4 + 2] = make_float2(v.z, v.z);
            wsd[e * WDSTR + k4 * 4 + 3] = make_float2(v.w, v.w);
        }
        __syncthreads();

        const ull* wsu = (const ull*)wsd;
#pragma unroll 8
        for (int k = 0; k < KC; k++) {
            ull a[4];
#pragma unroll
            for (int i = 0; i < 4; i++)
                a[i] = *(const ull*)&xs_t[k * XTSTR + 2 * (tr + 32 * i)];
#pragma unroll
            for (int j = 0; j < 8; j++) {
                ull b = wsu[(tc + 8 * j) * WDSTR + k];
#pragma unroll
                for (int i = 0; i < 4; i++)
                    fma_f32x2(acc[i][j], a[i], b);
            }
        }
        __syncthreads();
    }

    // write partial logits: acc lanes = tokens (2p, 2p+1), expert e=tc+8j
    float* plog = g_plog + (size_t)ks * NTOK * E;
#pragma unroll
    for (int i = 0; i < 4; i++) {
        const int p = tr + 32 * i;
        float* row0 = plog + (size_t)(n0 + 2 * p) * E;
#pragma unroll
        for (int j = 0; j < 8; j++) {
            float2 v = *(float2*)&acc[i][j];
            row0[tc + 8 * j] = v.x;
            row0[E + tc + 8 * j] = v.y;
        }
    }

    // sum-of-squares reduce (reuse xs_t smem)
    float* ssm = xs_t;   // needs 8*256 floats
#pragma unroll
    for (int j = 0; j < 8; j++) ssm[j * 256 + tid] = ssp[j];
    __syncthreads();
    {
        float ssum = 0.0f;
        const int jj = tid >> 5;
        const int r0 = tid & 31;
#pragma unroll
        for (int u = 0; u < 8; u++) ssum += ssm[jj * 256 + r0 * 8 + u];
        g_ss[ks * NTOK + n0 + tid] = ssum;
    }
}

// ---------------------------------------------------------------------------
// Kernel 5: reduce split-K, rms factor, top-4. One warp per token.
// ---------------------------------------------------------------------------
__global__ void __launch_bounds__(256) gate_final(float* __restrict__ out_w,
                                                  float* __restrict__ out_i) {
    const int warp = threadIdx.x >> 5;
    const int lane = threadIdx.x & 31;
    const int n = blockIdx.x * 8 + warp;

    float l0 = 0.0f, l1 = 0.0f, ss = 0.0f;
#pragma unroll
    for (int ks = 0; ks < KSPLIT; ks++) {
        const float* p = g_plog + (size_t)ks * NTOK * E + (size_t)n * E;
        l0 += p[lane];
        l1 += p[lane + 32];
        ss += g_ss[ks * NTOK + n];
    }
    const float f = rsqrtf(ss * (1.0f / H) + EPS);
    l0 *= f; l1 *= f;

    float wk[TOPK]; int ik[TOPK];
#pragma unroll
    for (int k = 0; k < TOPK; k++) {
        float v = l0; int idx = lane;
        if (l1 > v) { v = l1; idx = lane + 32; }
        // warp butterfly argmax: lower index wins ties (matches jax.lax.top_k)
#pragma unroll
        for (int off = 16; off; off >>= 1) {
            float ov = __shfl_xor_sync(0xffffffffu, v, off);
            int   oi = __shfl_xor_sync(0xffffffffu, idx, off);
            if (ov > v || (ov == v && oi < idx)) { v = ov; idx = oi; }
        }
        wk[k] = v; ik[k] = idx;
        if (idx == lane)      l0 = -3.4e38f;
        if (idx == lane + 32) l1 = -3.4e38f;
    }

    if (lane == 0) {
        const float m = wk[0];
        float p[TOPK], psum = 0.0f;
#pragma unroll
        for (int k = 0; k < TOPK; k++) { p[k] = __expf(wk[k] - m); psum += p[k]; }
        const float inv = 1.0f / fmaxf(psum, 1e-20f);
#pragma unroll
        for (int k = 0; k < TOPK; k++) {
            out_w[n * TOPK + k] = p[k] * inv;
            out_i[n * TOPK + k] = (float)ik[k];
        }
    }
}

// ---------------------------------------------------------------------------
extern "C" void kernel_launch(void* const* d_in, const int* in_sizes, int n_in,
                              void* d_out, int out_size) {
    const float* x      = (const float*)d_in[0];   // [B,S,H]
    const int*   packed = (const int*)  d_in[1];   // [B,S]
    const int*   mm     = (const int*)  d_in[2];   // [B,S]
    const float* scale  = (const float*)d_in[3];   // [H]
    const float* proj_w = (const float*)d_in[4];   // [E,H]

    float* out = (float*)d_out;
    const size_t mask_elems = (size_t)Bsz * S * S;           // 33554432
    float* full_out = out;
    float* slid_out = out + mask_elems;
    float* wts_out  = out + 2 * mask_elems;
    float* idx_out  = wts_out + (size_t)NTOK * TOPK;

    static cudaStream_t s2 = nullptr;
    static cudaEvent_t evA = nullptr, evB = nullptr;
    if (s2 == nullptr) {
        cudaStreamCreateWithFlags(&s2, cudaStreamNonBlocking);
        cudaEventCreateWithFlags(&evA, cudaEventDisableTiming);
        cudaEventCreateWithFlags(&evB, cudaEventDisableTiming);
        cudaFuncSetAttribute(gate_gemm, cudaFuncAttributeMaxDynamicSharedMemorySize, SMEM_GEMM);
    }

    gid_kernel<<<Bsz, 1024>>>(mm, packed);

    // fork: mask (depends only on gid) runs concurrently with gate chain
    cudaEventRecord(evA, 0);
    cudaStreamWaitEvent(s2, evA, 0);
    mask_kernel<<<dim3(S, Bsz), 256, 0, s2>>>(packed, full_out, slid_out);
    cudaEventRecord(evB, s2);

    wp_kernel<<<(E * H + 255) / 256, 256>>>(proj_w, scale);
    gate_gemm<<<dim3(NTOK / TMB, KSPLIT), 256, SMEM_GEMM>>>(x);
    gate_final<<<NTOK / 8, 256>>>(wts_out, idx_out);

    // join
    cudaStreamWaitEvent(0, evB, 0);
}

// round 14
// speedup vs baseline: 1.1090x; 1.0263x over previous
#include <cuda_runtime.h>
#include <cuda_bf16.h>
#include <math.h>

#define H    2048
#define E    64
#define TOPK 4
#define SW   1024
#define Bsz  2
#define S    4096
#define NEGF (-3.402823466e+38f)
#define EPS  1e-6f
#define INV_SQRT_H 0.02209708691207961f   // 1/sqrt(2048)

#define NTOK   (Bsz * S)          // 8192 tokens
#define KSPLIT 8
#define KSEG   (H / KSPLIT)       // 256
#define KC     32                 // k chunk per stage
#define NSTAGE (KSEG / KC)        // 8
#define TMB    128                // tokens per gemm block
#define XSTR   36                 // smem row stride (floats): mult of 4 (cp16), pad 4 (banks)

#define XS_FLOATS (TMB * XSTR)    // 4608
#define WS_FLOATS (E * XSTR)      // 2304
#define BUF_FLOATS (XS_FLOATS + WS_FLOATS)       // 6912
#define SMEM_GEMM (2 * BUF_FLOATS * 4)           // 55296 B

typedef unsigned long long ull;

// scratch (__device__ globals: allocation-free)
__device__ int   g_gid[Bsz * S];
__device__ int   g_vstart[Bsz * S];
__device__ int   g_vend[Bsz * S];
__device__ int   g_dstart[Bsz * 8];
__device__ int   g_dend[Bsz * 8];
__device__ float g_wp[E * H];                  // proj_w * scale * H^-0.5
__device__ float g_plog[KSPLIT * NTOK * E];    // partial logits
__device__ float g_ss[KSPLIT * NTOK];          // partial sum-of-squares

__device__ __forceinline__ void fma_f32x2(ull& d, ull a, ull b) {
    asm("fma.rn.f32x2 %0, %1, %2, %0;" : "+l"(d) : "l"(a), "l"(b));
}

__device__ __forceinline__ void cp16(void* dst_smem, const void* src) {
    unsigned d = (unsigned)__cvta_generic_to_shared(dst_smem);
    asm volatile("cp.async.cg.shared.global [%0], [%1], 16;" :: "r"(d), "l"(src));
}

// ---------------------------------------------------------------------------
// Kernel 1: vision group ids + doc/vision interval endpoints
// ---------------------------------------------------------------------------
__global__ void __launch_bounds__(1024) gid_kernel(const int* __restrict__ mm,
                                                   const int* __restrict__ packed) {
    const int b = blockIdx.x;
    const int* m = mm + b * S;
    const int* p = packed + b * S;
    int* g = g_gid + b * S;
    const int t = threadIdx.x;
    const int lane = t & 31, warp = t >> 5;
    const int base = t * 4;

    int isv[5], st[4];
    int cnt = 0;
#pragma unroll
    for (int i = 0; i < 4; i++) {
        int pos = base + i;
        int mv = m[pos];
        int v = (mv == 1 || mv == 2) ? 1 : 0;
        int pv = 0;
        if (pos > 0) {
            int pm = m[pos - 1];
            pv = (pm == 1 || pm == 2) ? 1 : 0;
        }
        int s = (v && !pv) ? 1 : 0;
        isv[i] = v; st[i] = s; cnt += s;
    }
    {
        int pos = base + 4;
        int nv = 0;
        if (pos < S) {
            int nm = m[pos];
            nv = (nm == 1 || nm == 2) ? 1 : 0;
        }
        isv[4] = nv;
    }

    // doc interval endpoints (packed is sorted per row, ids 0..4)
#pragma unroll
    for (int i = 0; i < 4; i++) {
        int pos = base + i;
        int v = p[pos];
        int prev = (pos > 0) ? p[pos - 1] : -1;
        int next = (pos < S - 1) ? p[pos + 1] : -1;
        if (v != prev && v >= 0 && v < 8) g_dstart[b * 8 + v] = pos;
        if (v != next && v >= 0 && v < 8) g_dend[b * 8 + v] = pos;
    }

    // warp inclusive scan
    int inc = cnt;
#pragma unroll
    for (int off = 1; off < 32; off <<= 1) {
        int v = __shfl_up_sync(0xffffffffu, inc, off);
        if (lane >= off) inc += v;
    }
    __shared__ int wsum[32];
    if (lane == 31) wsum[warp] = inc;
    __syncthreads();
    if (warp == 0) {
        int v = wsum[lane];
#pragma unroll
        for (int off = 1; off < 32; off <<= 1) {
            int u = __shfl_up_sync(0xffffffffu, v, off);
            if (lane >= off) v += u;
        }
        wsum[lane] = v;
    }
    __syncthreads();
    int run = ((warp > 0) ? wsum[warp - 1] : 0) + inc - cnt;
#pragma unroll
    for (int i = 0; i < 4; i++) {
        run += st[i];
        int pos = base + i;
        int gv = isv[i] ? (run - 1) : -1;
        g[pos] = gv;
        if (gv >= 0) {
            if (st[i]) g_vstart[b * S + gv] = pos;
            if (!isv[i + 1] || pos == S - 1) g_vend[b * S + gv] = pos;
        }
    }
}

// ---------------------------------------------------------------------------
// Kernel 2: masks as interval fills. grid = (S, B), 256 threads.
// ---------------------------------------------------------------------------
__global__ void __launch_bounds__(256) mask_kernel(const int* __restrict__ packed,
                                                   float* __restrict__ full_out,
                                                   float* __restrict__ slid_out) {
    const int q = blockIdx.x;
    const int b = blockIdx.y;
    const int pq = __ldg(&packed[b * S + q]);

    int flo = 1, fhi = 0;
    int alo = 1, ahi = 0;
    int clo = 1, chi = 0;
    if (pq > 0) {
        const int dlo = g_dstart[b * 8 + pq];
        const int dhi = g_dend[b * 8 + pq];
        flo = dlo; fhi = q;
        alo = max(dlo, q - SW + 1); ahi = q;
        const int gq = g_gid[b * S + q];
        if (gq >= 0) {
            clo = max(g_vstart[b * S + gq], dlo);
            chi = min(g_vend[b * S + gq], dhi);
        }
    }

    const size_t rowoff = ((size_t)b * S + (size_t)q) * (size_t)S;
    float4* fo = (float4*)(full_out + rowoff);
    float4* so = (float4*)(slid_out + rowoff);

#pragma unroll
    for (int it = 0; it < 4; it++) {
        const int c = threadIdx.x + it * 256;
        const int kv = c * 4;
        float4 f, sl;
        f.x = (kv + 0 >= flo && kv + 0 <= fhi) ? 0.0f : NEGF;
        f.y = (kv + 1 >= flo && kv + 1 <= fhi) ? 0.0f : NEGF;
        f.z = (kv + 2 >= flo && kv + 2 <= fhi) ? 0.0f : NEGF;
        f.w = (kv + 3 >= flo && kv + 3 <= fhi) ? 0.0f : NEGF;
        sl.x = ((kv + 0 >= alo && kv + 0 <= ahi) || (kv + 0 >= clo && kv + 0 <= chi)) ? 0.0f : NEGF;
        sl.y = ((kv + 1 >= alo && kv + 1 <= ahi) || (kv + 1 >= clo && kv + 1 <= chi)) ? 0.0f : NEGF;
        sl.z = ((kv + 2 >= alo && kv + 2 <= ahi) || (kv + 2 >= clo && kv + 2 <= chi)) ? 0.0f : NEGF;
        sl.w = ((kv + 3 >= alo && kv + 3 <= ahi) || (kv + 3 >= clo && kv + 3 <= chi)) ? 0.0f : NEGF;
        __stcs(&fo[c], f);
        __stcs(&so[c], sl);
    }
}

// ---------------------------------------------------------------------------
// Kernel 3: fold scale*H^-0.5 into proj_w
// ---------------------------------------------------------------------------
__global__ void __launch_bounds__(256) wp_kernel(const float* __restrict__ proj_w,
                                                 const float* __restrict__ scale) {
    int i = blockIdx.x * 256 + threadIdx.x;
    if (i < E * H) {
        g_wp[i] = proj_w[i] * scale[i & (H - 1)] * INV_SQRT_H;
    }
}

// ---------------------------------------------------------------------------
// Kernel 4: gate GEMM, split-K, cp.async double-buffered, NATURAL layouts.
// grid = (NTOK/TMB, KSPLIT) = (64, 8). 256 threads, 2 blocks/SM.
// Thread tile: 4 tokens x 8 experts, k-pair-packed f32x2 acc = 64 regs.
// Per k-pair: 4 LDS.64 (A) + 8 LDS.64 (B) + 32 FFMA2.
// Sum-of-squares recovered by re-reading the landed x tile from smem.
// ---------------------------------------------------------------------------
__device__ __forceinline__ void gemm_prefetch(const float* __restrict__ x,
                                              int n0, int kb, int tid,
                                              float* xsb, float* wsb) {
#pragma unroll
    for (int t = 0; t < 4; t++) {
        int idx = tid + t * 256;
        int row = idx >> 3;        // 0..127
        int col = idx & 7;
        cp16(&xsb[row * XSTR + col * 4], x + (size_t)(n0 + row) * H + kb + col * 4);
    }
#pragma unroll
    for (int t = 0; t < 2; t++) {
        int idx = tid + t * 256;
        int row = idx >> 3;        // 0..63
        int col = idx & 7;
        cp16(&wsb[row * XSTR + col * 4], g_wp + (size_t)row * H + kb + col * 4);
    }
    asm volatile("cp.async.commit_group;");
}

__global__ void __launch_bounds__(256, 2) gate_gemm(const float* __restrict__ x) {
    extern __shared__ float sm[];
    float* xs[2] = { sm, sm + BUF_FLOATS };
    float* ws[2] = { sm + XS_FLOATS, sm + BUF_FLOATS + XS_FLOATS };

    const int n0 = blockIdx.x * TMB;
    const int ks = blockIdx.y;
    const int kb0 = ks * KSEG;

    const int tid = threadIdx.x;
    const int tr = tid >> 3;    // 0..31 token group (tokens tr+32i)
    const int tc = tid & 7;     // 0..7 expert group (experts tc+8j)

    ull acc[4][8];
#pragma unroll
    for (int i = 0; i < 4; i++)
#pragma unroll
        for (int j = 0; j < 8; j++) acc[i][j] = 0ull;
    float ssp = 0.0f;           // partial ss for token row (tid>>1), half (tid&1)

    gemm_prefetch(x, n0, kb0, tid, xs[0], ws[0]);

    for (int s = 0; s < NSTAGE; s++) {
        if (s + 1 < NSTAGE) {
            gemm_prefetch(x, n0, kb0 + (s + 1) * KC, tid, xs[(s + 1) & 1], ws[(s + 1) & 1]);
            asm volatile("cp.async.wait_group 1;" ::: "memory");
        } else {
            asm volatile("cp.async.wait_group 0;" ::: "memory");
        }
        __syncthreads();

        const float* xsb = xs[s & 1];
        const float* wsb = ws[s & 1];

        // ss: re-read x tile (row = tid>>1, half = tid&1 -> 16 floats)
        {
            const float* r = &xsb[(tid >> 1) * XSTR + (tid & 1) * 16];
#pragma unroll
            for (int q = 0; q < 4; q++) {
                float4 v = *(const float4*)(r + q * 4);
                ssp += v.x * v.x + v.y * v.y + v.z * v.z + v.w * v.w;
            }
        }

#pragma unroll
        for (int k2 = 0; k2 < KC / 2; k2++) {
            ull a[4], b[8];
#pragma unroll
            for (int i = 0; i < 4; i++)
                a[i] = *(const ull*)&xsb[(tr + 32 * i) * XSTR + 2 * k2];
#pragma unroll
            for (int j = 0; j < 8; j++)
                b[j] = *(const ull*)&wsb[(tc + 8 * j) * XSTR + 2 * k2];
#pragma unroll
            for (int i = 0; i < 4; i++)
#pragma unroll
                for (int j = 0; j < 8; j++)
                    fma_f32x2(acc[i][j], a[i], b[j]);
        }
        __syncthreads();
    }

    // write partial logits (k-pair acc -> horizontal add)
    float* plog = g_plog + (size_t)ks * NTOK * E;
#pragma unroll
    for (int i = 0; i < 4; i++) {
        const int n = n0 + tr + 32 * i;
#pragma unroll
        for (int j = 0; j < 8; j++) {
            float2 v = *(float2*)&acc[i][j];
            plog[(size_t)n * E + tc + 8 * j] = v.x + v.y;
        }
    }

    // ss reduce: two threads per token row
    float* ssm = sm;   // smem reuse after final sync
    __syncthreads();
    ssm[tid] = ssp;
    __syncthreads();
    if (tid < TMB)
        g_ss[ks * NTOK + n0 + tid] = ssm[2 * tid] + ssm[2 * tid + 1];
}

// ---------------------------------------------------------------------------
// Kernel 5: reduce split-K, rms factor, top-4. One warp per token.
// ---------------------------------------------------------------------------
__global__ void __launch_bounds__(256) gate_final(float* __restrict__ out_w,
                                                  float* __restrict__ out_i) {
    const int warp = threadIdx.x >> 5;
    const int lane = threadIdx.x & 31;
    const int n = blockIdx.x * 8 + warp;

    float l0 = 0.0f, l1 = 0.0f, ss = 0.0f;
#pragma unroll
    for (int ks = 0; ks < KSPLIT; ks++) {
        const float* p = g_plog + (size_t)ks * NTOK * E + (size_t)n * E;
        l0 += p[lane];
        l1 += p[lane + 32];
        ss += g_ss[ks * NTOK + n];
    }
    const float f = rsqrtf(ss * (1.0f / H) + EPS);
    l0 *= f; l1 *= f;

    float wk[TOPK]; int ik[TOPK];
#pragma unroll
    for (int k = 0; k < TOPK; k++) {
        float v = l0; int idx = lane;
        if (l1 > v) { v = l1; idx = lane + 32; }
        // warp butterfly argmax: lower index wins ties (matches jax.lax.top_k)
#pragma unroll
        for (int off = 16; off; off >>= 1) {
            float ov = __shfl_xor_sync(0xffffffffu, v, off);
            int   oi = __shfl_xor_sync(0xffffffffu, idx, off);
            if (ov > v || (ov == v && oi < idx)) { v = ov; idx = oi; }
        }
        wk[k] = v; ik[k] = idx;
        if (idx == lane)      l0 = -3.4e38f;
        if (idx == lane + 32) l1 = -3.4e38f;
    }

    if (lane == 0) {
        const float m = wk[0];
        float p[TOPK], psum = 0.0f;
#pragma unroll
        for (int k = 0; k < TOPK; k++) { p[k] = __expf(wk[k] - m); psum += p[k]; }
        const float inv = 1.0f / fmaxf(psum, 1e-20f);
#pragma unroll
        for (int k = 0; k < TOPK; k++) {
            out_w[n * TOPK + k] = p[k] * inv;
            out_i[n * TOPK + k] = (float)ik[k];
        }
    }
}

// ---------------------------------------------------------------------------
extern "C" void kernel_launch(void* const* d_in, const int* in_sizes, int n_in,
                              void* d_out, int out_size) {
    const float* x      = (const float*)d_in[0];   // [B,S,H]
    const int*   packed = (const int*)  d_in[1];   // [B,S]
    const int*   mm     = (const int*)  d_in[2];   // [B,S]
    const float* scale  = (const float*)d_in[3];   // [H]
    const float* proj_w = (const float*)d_in[4];   // [E,H]

    float* out = (float*)d_out;
    const size_t mask_elems = (size_t)Bsz * S * S;           // 33554432
    float* full_out = out;
    float* slid_out = out + mask_elems;
    float* wts_out  = out + 2 * mask_elems;
    float* idx_out  = wts_out + (size_t)NTOK * TOPK;

    static cudaStream_t s2 = nullptr;
    static cudaEvent_t evA = nullptr, evB = nullptr;
    if (s2 == nullptr) {
        cudaStreamCreateWithFlags(&s2, cudaStreamNonBlocking);
        cudaEventCreateWithFlags(&evA, cudaEventDisableTiming);
        cudaEventCreateWithFlags(&evB, cudaEventDisableTiming);
        cudaFuncSetAttribute(gate_gemm, cudaFuncAttributeMaxDynamicSharedMemorySize, SMEM_GEMM);
    }

    gid_kernel<<<Bsz, 1024>>>(mm, packed);

    // fork: mask (depends only on gid) runs concurrently with gate chain
    cudaEventRecord(evA, 0);
    cudaStreamWaitEvent(s2, evA, 0);
    mask_kernel<<<dim3(S, Bsz), 256, 0, s2>>>(packed, full_out, slid_out);
    cudaEventRecord(evB, s2);

    wp_kernel<<<(E * H + 255) / 256, 256>>>(proj_w, scale);
    gate_gemm<<<dim3(NTOK / TMB, KSPLIT), 256, SMEM_GEMM>>>(x);
    gate_final<<<NTOK / 8, 256>>>(wts_out, idx_out);

    // join
    cudaStreamWaitEvent(0, evB, 0);
}